// round 1
// baseline (speedup 1.0000x reference)
#include <cuda_runtime.h>
#include <cuda_bf16.h>
#include <math.h>

// Problem constants
#define BATCH 2
#define SEQ   2048
#define DIM   2048
#define NHEAD 16
#define HDIM  128
#define MTOT  (BATCH * SEQ)       // 4096 rows
#define EPSV  1.1920928955078125e-07f

// Scratch (device globals; no dynamic allocation allowed)
__device__ float g_Q[MTOT * DIM];
__device__ float g_K[MTOT * DIM];
__device__ float g_V[MTOT * DIM];
__device__ float g_Y[MTOT * DIM];

// ---------------------------------------------------------------------------
// SGEMM: C[M,N] = A[M,K] * B[N,K]^T   (both operands K-contiguous, fp32)
// 128x128 block tile, BK=16, 256 threads, 8x8 per thread.
// ---------------------------------------------------------------------------
__global__ __launch_bounds__(256) void sgemm_nt(const float* __restrict__ A,
                                                const float* __restrict__ B,
                                                float* __restrict__ C,
                                                int M, int N, int K)
{
    __shared__ float As[16][128];
    __shared__ float Bs[16][128];

    const int tid = threadIdx.x;
    const int m0 = blockIdx.y * 128;
    const int n0 = blockIdx.x * 128;
    const int tm = (tid >> 4) * 8;   // 0..120
    const int tn = (tid & 15) * 8;   // 0..120

    float acc[8][8];
#pragma unroll
    for (int i = 0; i < 8; i++)
#pragma unroll
        for (int j = 0; j < 8; j++) acc[i][j] = 0.0f;

    for (int k0 = 0; k0 < K; k0 += 16) {
        // Load A tile (128 rows x 16 cols) and B tile, store transposed.
#pragma unroll
        for (int e = 0; e < 2; e++) {
            int v = tid + e * 256;        // 0..511
            int row = v >> 2;             // 0..127
            int c4 = (v & 3) * 4;         // 0,4,8,12
            float4 a = *(const float4*)(A + (size_t)(m0 + row) * K + k0 + c4);
            As[c4 + 0][row] = a.x; As[c4 + 1][row] = a.y;
            As[c4 + 2][row] = a.z; As[c4 + 3][row] = a.w;
            float4 b = *(const float4*)(B + (size_t)(n0 + row) * K + k0 + c4);
            Bs[c4 + 0][row] = b.x; Bs[c4 + 1][row] = b.y;
            Bs[c4 + 2][row] = b.z; Bs[c4 + 3][row] = b.w;
        }
        __syncthreads();

#pragma unroll
        for (int kk = 0; kk < 16; kk++) {
            float4 a0 = *(const float4*)&As[kk][tm];
            float4 a1 = *(const float4*)&As[kk][tm + 4];
            float4 b0 = *(const float4*)&Bs[kk][tn];
            float4 b1 = *(const float4*)&Bs[kk][tn + 4];
            float af[8] = {a0.x, a0.y, a0.z, a0.w, a1.x, a1.y, a1.z, a1.w};
            float bf[8] = {b0.x, b0.y, b0.z, b0.w, b1.x, b1.y, b1.z, b1.w};
#pragma unroll
            for (int i = 0; i < 8; i++)
#pragma unroll
                for (int j = 0; j < 8; j++)
                    acc[i][j] = fmaf(af[i], bf[j], acc[i][j]);
        }
        __syncthreads();
    }

#pragma unroll
    for (int i = 0; i < 8; i++) {
        float* crow = C + (size_t)(m0 + tm + i) * N + n0 + tn;
        float4 o0 = make_float4(acc[i][0], acc[i][1], acc[i][2], acc[i][3]);
        float4 o1 = make_float4(acc[i][4], acc[i][5], acc[i][6], acc[i][7]);
        ((float4*)crow)[0] = o0;
        ((float4*)crow)[1] = o1;
    }
}

// ---------------------------------------------------------------------------
// Per-head RMSNorm + RoPE (in place). One warp per head, 4 heads per block.
// Layout: T[(b*SEQ+s)*DIM + h*HDIM + d]
// ---------------------------------------------------------------------------
__global__ __launch_bounds__(128) void rmsnorm_rope(float* __restrict__ T)
{
    const int b = blockIdx.z;
    const int s = blockIdx.y;
    const int warp = threadIdx.x >> 5;
    const int lane = threadIdx.x & 31;
    const int h = blockIdx.x * 4 + warp;

    float* row = T + ((size_t)(b * SEQ + s)) * DIM + h * HDIM;

    // Each lane owns pairs p = lane and p = lane+32 (elements p, p+64)
    float x1a = row[lane];
    float x1b = row[lane + 32];
    float x2a = row[lane + 64];
    float x2b = row[lane + 96];

    float ss = x1a * x1a + x1b * x1b + x2a * x2a + x2b * x2b;
#pragma unroll
    for (int off = 16; off > 0; off >>= 1)
        ss += __shfl_xor_sync(0xffffffffu, ss, off);

    float rnorm = rsqrtf(ss * (1.0f / 128.0f) + EPSV);
    x1a *= rnorm; x1b *= rnorm; x2a *= rnorm; x2b *= rnorm;

    const float LN1E4 = 9.210340371976184f;   // ln(10000)
    float pos = (float)s;

    // pair a: p = lane
    {
        float expo = (float)lane * (1.0f / 64.0f);
        float ang = pos * __expf(-expo * LN1E4);
        float sn, cs;
        sincosf(ang, &sn, &cs);
        row[lane]      =  x1a * cs + x2a * sn;
        row[lane + 64] = -x1a * sn + x2a * cs;
    }
    // pair b: p = lane + 32
    {
        float expo = (float)(lane + 32) * (1.0f / 64.0f);
        float ang = pos * __expf(-expo * LN1E4);
        float sn, cs;
        sincosf(ang, &sn, &cs);
        row[lane + 32] =  x1b * cs + x2b * sn;
        row[lane + 96] = -x1b * sn + x2b * cs;
    }
}

// ---------------------------------------------------------------------------
// Causal flash attention, fp32. Block = 128 query rows, 256 threads:
// thread pair (2 lanes) per row, each handles 64 of the 128 head dims.
// K/V tiles of 32 keys staged in smem; score tile staged in smem.
// ---------------------------------------------------------------------------
__global__ __launch_bounds__(256) void attn_kernel(const float* __restrict__ Q,
                                                   const float* __restrict__ K,
                                                   const float* __restrict__ V,
                                                   float* __restrict__ Y)
{
    __shared__ float4 Ks[32][32];   // [key][dvec]  16KB
    __shared__ float4 Vs[32][32];   // 16KB
    __shared__ float  Ss[32][128];  // [key][row]   16KB

    const int tid = threadIdx.x;
    const int b = blockIdx.z;
    const int h = blockIdx.y;
    const int m0 = blockIdx.x * 128;
    const int row = tid >> 1;       // 0..127
    const int hf = tid & 1;         // which half of head dim
    const int r = m0 + row;

    const float* qrow = Q + ((size_t)(b * SEQ + r)) * DIM + h * HDIM + hf * 64;
    float4 q[16];
#pragma unroll
    for (int i = 0; i < 16; i++) q[i] = ((const float4*)qrow)[i];

    float4 acc[16];
#pragma unroll
    for (int i = 0; i < 16; i++) acc[i] = make_float4(0.f, 0.f, 0.f, 0.f);

    float mI = -1e30f, lI = 0.0f;
    const float scale = 0.08838834764831845f;   // 1/sqrt(128)
    const int nEnd = m0 + 128;                  // causal bound (exclusive)

    for (int n0 = 0; n0 < nEnd; n0 += 32) {
        __syncthreads();
        // Stage 32 keys + values
#pragma unroll
        for (int e = 0; e < 4; e++) {
            int idx = tid + e * 256;            // 0..1023
            int j = idx >> 5;
            int dv = idx & 31;
            size_t g = ((size_t)(b * SEQ + n0 + j)) * DIM + h * HDIM + dv * 4;
            Ks[j][dv] = *(const float4*)(K + g);
            Vs[j][dv] = *(const float4*)(V + g);
        }
        __syncthreads();

        // Pass 1: scores for this tile + tile max
        float mTile = -1e30f;
#pragma unroll
        for (int j = 0; j < 32; j++) {
            float s = 0.0f;
#pragma unroll
            for (int i = 0; i < 16; i++) {
                float4 kv = Ks[j][hf * 16 + i];
                float4 qq = q[i];
                s = fmaf(qq.x, kv.x, s);
                s = fmaf(qq.y, kv.y, s);
                s = fmaf(qq.z, kv.z, s);
                s = fmaf(qq.w, kv.w, s);
            }
            s += __shfl_xor_sync(0xffffffffu, s, 1);   // combine the two halves
            s *= scale;
            if (n0 + j > r) s = -1e30f;                 // causal mask
            mTile = fmaxf(mTile, s);
            if (hf == 0) Ss[j][row] = s;
        }
        __syncwarp();

        float mNew = fmaxf(mI, mTile);
        float resc = __expf(mI - mNew);
        mI = mNew;
        lI *= resc;
#pragma unroll
        for (int i = 0; i < 16; i++) {
            acc[i].x *= resc; acc[i].y *= resc;
            acc[i].z *= resc; acc[i].w *= resc;
        }

        // Pass 2: p = exp(s - m), accumulate p*V
#pragma unroll
        for (int j = 0; j < 32; j++) {
            float p = __expf(Ss[j][row] - mNew);
            lI += p;
#pragma unroll
            for (int i = 0; i < 16; i++) {
                float4 vv = Vs[j][hf * 16 + i];
                acc[i].x = fmaf(p, vv.x, acc[i].x);
                acc[i].y = fmaf(p, vv.y, acc[i].y);
                acc[i].z = fmaf(p, vv.z, acc[i].z);
                acc[i].w = fmaf(p, vv.w, acc[i].w);
            }
        }
    }

    float inv = 1.0f / lI;
    float* yrow = Y + ((size_t)(b * SEQ + r)) * DIM + h * HDIM + hf * 64;
#pragma unroll
    for (int i = 0; i < 16; i++) {
        float4 o = make_float4(acc[i].x * inv, acc[i].y * inv,
                               acc[i].z * inv, acc[i].w * inv);
        ((float4*)yrow)[i] = o;
    }
}

// ---------------------------------------------------------------------------
// Launch
// ---------------------------------------------------------------------------
extern "C" void kernel_launch(void* const* d_in, const int* in_sizes, int n_in,
                              void* d_out, int out_size)
{
    const float* x  = (const float*)d_in[0];
    const float* Wq = (const float*)d_in[1];
    const float* Wk = (const float*)d_in[2];
    const float* Wv = (const float*)d_in[3];
    const float* Wo = (const float*)d_in[4];
    float* out = (float*)d_out;

    float* Qp; cudaGetSymbolAddress((void**)&Qp, g_Q);
    float* Kp; cudaGetSymbolAddress((void**)&Kp, g_K);
    float* Vp; cudaGetSymbolAddress((void**)&Vp, g_V);
    float* Yp; cudaGetSymbolAddress((void**)&Yp, g_Y);

    dim3 gGemm(DIM / 128, MTOT / 128);   // (16, 32)
    sgemm_nt<<<gGemm, 256>>>(x, Wq, Qp, MTOT, DIM, DIM);
    sgemm_nt<<<gGemm, 256>>>(x, Wk, Kp, MTOT, DIM, DIM);
    sgemm_nt<<<gGemm, 256>>>(x, Wv, Vp, MTOT, DIM, DIM);

    dim3 gNorm(NHEAD / 4, SEQ, BATCH);
    rmsnorm_rope<<<gNorm, 128>>>(Qp);
    rmsnorm_rope<<<gNorm, 128>>>(Kp);

    dim3 gAttn(SEQ / 128, NHEAD, BATCH); // (16, 16, 2)
    attn_kernel<<<gAttn, 256>>>(Qp, Kp, Vp, Yp);

    sgemm_nt<<<gGemm, 256>>>(Yp, Wo, out, MTOT, DIM, DIM);
}

// round 2
// speedup vs baseline: 1.4268x; 1.4268x over previous
#include <cuda_runtime.h>
#include <cuda_bf16.h>
#include <math.h>
#include <stdint.h>

// Problem constants
#define BATCH 2
#define SEQ   2048
#define DIM   2048
#define NHEAD 16
#define HDIM  128
#define MTOT  (BATCH * SEQ)       // 4096 rows
#define EPSV  1.1920928955078125e-07f

// Scratch (device globals; no dynamic allocation allowed)
__device__ float g_Q[MTOT * DIM];
__device__ float g_K[MTOT * DIM];
__device__ float g_V[MTOT * DIM];
__device__ float g_Y[MTOT * DIM];

// ---------------------------------------------------------------------------
// TF32 tensor-core GEMM: C[M,N] = A[M,K] * B[N,K]^T
// M=4096 (or MTOT), N=2048, K=2048 fixed strides (K-contiguous operands).
// Block 128x128, BK=16, 256 threads, 8 warps (2x4), warp tile 64x32.
// Smem stored in mma-fragment order: conflict-free LDS.128 / LDS.64.
// ---------------------------------------------------------------------------
__device__ __forceinline__ uint32_t f2tf32(float x) {
    uint32_t r;
    asm("cvt.rna.tf32.f32 %0, %1;" : "=r"(r) : "f"(x));
    return r;
}

__device__ __forceinline__ void mma_tf32(float c[4],
                                         uint32_t a0, uint32_t a1, uint32_t a2, uint32_t a3,
                                         uint32_t b0, uint32_t b1)
{
    asm volatile(
        "mma.sync.aligned.m16n8k8.row.col.f32.tf32.tf32.f32 "
        "{%0,%1,%2,%3}, {%4,%5,%6,%7}, {%8,%9}, {%0,%1,%2,%3};\n"
        : "+f"(c[0]), "+f"(c[1]), "+f"(c[2]), "+f"(c[3])
        : "r"(a0), "r"(a1), "r"(a2), "r"(a3), "r"(b0), "r"(b1));
}

__global__ __launch_bounds__(256) void gemm_tf32(const float* __restrict__ A,
                                                 const float* __restrict__ B,
                                                 float* __restrict__ C)
{
    // Fragment-order smem. A: 8 mtiles x 2 ksteps x 32 lanes x 4 floats = 2048.
    //                      B: 16 ntiles x 2 ksteps x 32 lanes x 2 floats = 2048.
    __shared__ float As[2][2048];
    __shared__ float Bs[2][2048];

    const int tid  = threadIdx.x;
    const int lane = tid & 31;
    const int wid  = tid >> 5;
    const int wm   = wid >> 2;          // 0..1
    const int wn   = wid & 3;           // 0..3
    const int m0   = blockIdx.y * 128;
    const int n0   = blockIdx.x * 128;

    // global load mapping: 64 rows x 4 float4-cols per 256 threads, x2
    const int grow = tid >> 2;          // 0..63
    const int kq   = tid & 3;           // 0..3 (float4 column)
    const int ks   = kq >> 1;           // k-step 0..1
    const int sk   = kq & 1;            // k sub-slot

    float4 ra[2], rb[2];
    float c[4][4][4];
#pragma unroll
    for (int i = 0; i < 4; i++)
#pragma unroll
        for (int j = 0; j < 4; j++)
#pragma unroll
            for (int e = 0; e < 4; e++) c[i][j][e] = 0.0f;

    const int NIT = DIM / 16;   // 128

    // ---- prologue load ----
#pragma unroll
    for (int e = 0; e < 2; e++) {
        int r = grow + e * 64;
        ra[e] = *(const float4*)(A + (size_t)(m0 + r) * DIM + kq * 4);
        rb[e] = *(const float4*)(B + (size_t)(n0 + r) * DIM + kq * 4);
    }
    // ---- prologue store stage 0 ----
#pragma unroll
    for (int e = 0; e < 2; e++) {
        int r = grow + e * 64;
        int mt = r >> 4, mi = r & 15, g = mi & 7, mh = mi >> 3;
        float* ab = &As[0][(((mt * 2 + ks) * 32 + g * 4) << 2) + mh + 2 * sk];
        float va[4] = {ra[e].x, ra[e].y, ra[e].z, ra[e].w};
#pragma unroll
        for (int j = 0; j < 4; j++) ab[j * 4] = __uint_as_float(f2tf32(va[j]));
        int nt = r >> 3, gb = r & 7;
        float* bb = &Bs[0][(((nt * 2 + ks) * 32 + gb * 4) << 1) + sk];
        float vb[4] = {rb[e].x, rb[e].y, rb[e].z, rb[e].w};
#pragma unroll
        for (int j = 0; j < 4; j++) bb[j * 2] = __uint_as_float(f2tf32(vb[j]));
    }
    __syncthreads();

    for (int it = 0; it < NIT; it++) {
        const int s = it & 1;
        if (it + 1 < NIT) {
            int k0 = (it + 1) * 16;
#pragma unroll
            for (int e = 0; e < 2; e++) {
                int r = grow + e * 64;
                ra[e] = *(const float4*)(A + (size_t)(m0 + r) * DIM + k0 + kq * 4);
                rb[e] = *(const float4*)(B + (size_t)(n0 + r) * DIM + k0 + kq * 4);
            }
        }

        // ---- compute on stage s ----
#pragma unroll
        for (int kk = 0; kk < 2; kk++) {
            uint32_t af[4][4];
            uint32_t bf[4][2];
#pragma unroll
            for (int i = 0; i < 4; i++) {
                int mt = wm * 4 + i;
                float4 t = *(const float4*)&As[s][(((mt * 2 + kk) * 32 + lane) << 2)];
                af[i][0] = __float_as_uint(t.x); af[i][1] = __float_as_uint(t.y);
                af[i][2] = __float_as_uint(t.z); af[i][3] = __float_as_uint(t.w);
            }
#pragma unroll
            for (int j = 0; j < 4; j++) {
                int nt = wn * 4 + j;
                float2 t = *(const float2*)&Bs[s][(((nt * 2 + kk) * 32 + lane) << 1)];
                bf[j][0] = __float_as_uint(t.x); bf[j][1] = __float_as_uint(t.y);
            }
#pragma unroll
            for (int i = 0; i < 4; i++)
#pragma unroll
                for (int j = 0; j < 4; j++)
                    mma_tf32(c[i][j], af[i][0], af[i][1], af[i][2], af[i][3],
                             bf[j][0], bf[j][1]);
        }

        if (it + 1 < NIT) {
            const int ns = 1 - s;
#pragma unroll
            for (int e = 0; e < 2; e++) {
                int r = grow + e * 64;
                int mt = r >> 4, mi = r & 15, g = mi & 7, mh = mi >> 3;
                float* ab = &As[ns][(((mt * 2 + ks) * 32 + g * 4) << 2) + mh + 2 * sk];
                float va[4] = {ra[e].x, ra[e].y, ra[e].z, ra[e].w};
#pragma unroll
                for (int j = 0; j < 4; j++) ab[j * 4] = __uint_as_float(f2tf32(va[j]));
                int nt = r >> 3, gb = r & 7;
                float* bb = &Bs[ns][(((nt * 2 + ks) * 32 + gb * 4) << 1) + sk];
                float vb[4] = {rb[e].x, rb[e].y, rb[e].z, rb[e].w};
#pragma unroll
                for (int j = 0; j < 4; j++) bb[j * 2] = __uint_as_float(f2tf32(vb[j]));
            }
            __syncthreads();
        }
    }

    // ---- epilogue ----
    const int g = lane >> 2;
    const int t = lane & 3;
#pragma unroll
    for (int i = 0; i < 4; i++) {
        int mbase = m0 + wm * 64 + i * 16;
#pragma unroll
        for (int j = 0; j < 4; j++) {
            int ncol = n0 + wn * 32 + j * 8 + t * 2;
            float2 lo = make_float2(c[i][j][0], c[i][j][1]);
            float2 hi = make_float2(c[i][j][2], c[i][j][3]);
            *(float2*)&C[(size_t)(mbase + g) * DIM + ncol]     = lo;
            *(float2*)&C[(size_t)(mbase + g + 8) * DIM + ncol] = hi;
        }
    }
}

// ---------------------------------------------------------------------------
// Per-head RMSNorm + RoPE (in place). One warp per head, 4 heads per block.
// ---------------------------------------------------------------------------
__global__ __launch_bounds__(128) void rmsnorm_rope(float* __restrict__ T)
{
    const int b = blockIdx.z;
    const int s = blockIdx.y;
    const int warp = threadIdx.x >> 5;
    const int lane = threadIdx.x & 31;
    const int h = blockIdx.x * 4 + warp;

    float* row = T + ((size_t)(b * SEQ + s)) * DIM + h * HDIM;

    float x1a = row[lane];
    float x1b = row[lane + 32];
    float x2a = row[lane + 64];
    float x2b = row[lane + 96];

    float ss = x1a * x1a + x1b * x1b + x2a * x2a + x2b * x2b;
#pragma unroll
    for (int off = 16; off > 0; off >>= 1)
        ss += __shfl_xor_sync(0xffffffffu, ss, off);

    float rnorm = rsqrtf(ss * (1.0f / 128.0f) + EPSV);
    x1a *= rnorm; x1b *= rnorm; x2a *= rnorm; x2b *= rnorm;

    const float LN1E4 = 9.210340371976184f;   // ln(10000)
    float pos = (float)s;

    {
        float expo = (float)lane * (1.0f / 64.0f);
        float ang = pos * __expf(-expo * LN1E4);
        float sn, cs;
        sincosf(ang, &sn, &cs);
        row[lane]      =  x1a * cs + x2a * sn;
        row[lane + 64] = -x1a * sn + x2a * cs;
    }
    {
        float expo = (float)(lane + 32) * (1.0f / 64.0f);
        float ang = pos * __expf(-expo * LN1E4);
        float sn, cs;
        sincosf(ang, &sn, &cs);
        row[lane + 32] =  x1b * cs + x2b * sn;
        row[lane + 96] = -x1b * sn + x2b * cs;
    }
}

// ---------------------------------------------------------------------------
// Causal flash attention, fp32 (unchanged from R1).
// ---------------------------------------------------------------------------
__global__ __launch_bounds__(256) void attn_kernel(const float* __restrict__ Q,
                                                   const float* __restrict__ K,
                                                   const float* __restrict__ V,
                                                   float* __restrict__ Y)
{
    __shared__ float4 Ks[32][32];
    __shared__ float4 Vs[32][32];
    __shared__ float  Ss[32][128];

    const int tid = threadIdx.x;
    const int b = blockIdx.z;
    const int h = blockIdx.y;
    const int m0 = blockIdx.x * 128;
    const int row = tid >> 1;
    const int hf = tid & 1;
    const int r = m0 + row;

    const float* qrow = Q + ((size_t)(b * SEQ + r)) * DIM + h * HDIM + hf * 64;
    float4 q[16];
#pragma unroll
    for (int i = 0; i < 16; i++) q[i] = ((const float4*)qrow)[i];

    float4 acc[16];
#pragma unroll
    for (int i = 0; i < 16; i++) acc[i] = make_float4(0.f, 0.f, 0.f, 0.f);

    float mI = -1e30f, lI = 0.0f;
    const float scale = 0.08838834764831845f;
    const int nEnd = m0 + 128;

    for (int n0 = 0; n0 < nEnd; n0 += 32) {
        __syncthreads();
#pragma unroll
        for (int e = 0; e < 4; e++) {
            int idx = tid + e * 256;
            int j = idx >> 5;
            int dv = idx & 31;
            size_t gofs = ((size_t)(b * SEQ + n0 + j)) * DIM + h * HDIM + dv * 4;
            Ks[j][dv] = *(const float4*)(K + gofs);
            Vs[j][dv] = *(const float4*)(V + gofs);
        }
        __syncthreads();

        float mTile = -1e30f;
#pragma unroll
        for (int j = 0; j < 32; j++) {
            float s = 0.0f;
#pragma unroll
            for (int i = 0; i < 16; i++) {
                float4 kv = Ks[j][hf * 16 + i];
                float4 qq = q[i];
                s = fmaf(qq.x, kv.x, s);
                s = fmaf(qq.y, kv.y, s);
                s = fmaf(qq.z, kv.z, s);
                s = fmaf(qq.w, kv.w, s);
            }
            s += __shfl_xor_sync(0xffffffffu, s, 1);
            s *= scale;
            if (n0 + j > r) s = -1e30f;
            mTile = fmaxf(mTile, s);
            if (hf == 0) Ss[j][row] = s;
        }
        __syncwarp();

        float mNew = fmaxf(mI, mTile);
        float resc = __expf(mI - mNew);
        mI = mNew;
        lI *= resc;
#pragma unroll
        for (int i = 0; i < 16; i++) {
            acc[i].x *= resc; acc[i].y *= resc;
            acc[i].z *= resc; acc[i].w *= resc;
        }

#pragma unroll
        for (int j = 0; j < 32; j++) {
            float p = __expf(Ss[j][row] - mNew);
            lI += p;
#pragma unroll
            for (int i = 0; i < 16; i++) {
                float4 vv = Vs[j][hf * 16 + i];
                acc[i].x = fmaf(p, vv.x, acc[i].x);
                acc[i].y = fmaf(p, vv.y, acc[i].y);
                acc[i].z = fmaf(p, vv.z, acc[i].z);
                acc[i].w = fmaf(p, vv.w, acc[i].w);
            }
        }
    }

    float inv = 1.0f / lI;
    float* yrow = Y + ((size_t)(b * SEQ + r)) * DIM + h * HDIM + hf * 64;
#pragma unroll
    for (int i = 0; i < 16; i++) {
        float4 o = make_float4(acc[i].x * inv, acc[i].y * inv,
                               acc[i].z * inv, acc[i].w * inv);
        ((float4*)yrow)[i] = o;
    }
}

// ---------------------------------------------------------------------------
// Launch
// ---------------------------------------------------------------------------
extern "C" void kernel_launch(void* const* d_in, const int* in_sizes, int n_in,
                              void* d_out, int out_size)
{
    const float* x  = (const float*)d_in[0];
    const float* Wq = (const float*)d_in[1];
    const float* Wk = (const float*)d_in[2];
    const float* Wv = (const float*)d_in[3];
    const float* Wo = (const float*)d_in[4];
    float* out = (float*)d_out;

    float* Qp; cudaGetSymbolAddress((void**)&Qp, g_Q);
    float* Kp; cudaGetSymbolAddress((void**)&Kp, g_K);
    float* Vp; cudaGetSymbolAddress((void**)&Vp, g_V);
    float* Yp; cudaGetSymbolAddress((void**)&Yp, g_Y);

    dim3 gGemm(DIM / 128, MTOT / 128);   // (16, 32)
    gemm_tf32<<<gGemm, 256>>>(x, Wq, Qp);
    gemm_tf32<<<gGemm, 256>>>(x, Wk, Kp);
    gemm_tf32<<<gGemm, 256>>>(x, Wv, Vp);

    dim3 gNorm(NHEAD / 4, SEQ, BATCH);
    rmsnorm_rope<<<gNorm, 128>>>(Qp);
    rmsnorm_rope<<<gNorm, 128>>>(Kp);

    dim3 gAttn(SEQ / 128, NHEAD, BATCH); // (16, 16, 2)
    attn_kernel<<<gAttn, 256>>>(Qp, Kp, Vp, Yp);

    gemm_tf32<<<gGemm, 256>>>(Yp, Wo, out);
}

// round 4
// speedup vs baseline: 1.7729x; 1.2426x over previous
#include <cuda_runtime.h>
#include <cuda_fp16.h>
#include <cuda_bf16.h>
#include <math.h>
#include <stdint.h>

#define BATCH 2
#define SEQ   2048
#define DIM   2048
#define NHEAD 16
#define HDIM  128
#define MTOT  (BATCH * SEQ)       // 4096
#define EPSV  1.1920928955078125e-07f

// fp32 scratch
__device__ float g_Q[MTOT * DIM];
__device__ float g_K[MTOT * DIM];
__device__ float g_V[MTOT * DIM];
// fp16 operands
__device__ __half g_xh[MTOT * DIM];
__device__ __half g_Wqh[DIM * DIM];
__device__ __half g_Wkh[DIM * DIM];
__device__ __half g_Wvh[DIM * DIM];
__device__ __half g_Woh[DIM * DIM];
__device__ __half g_Yh[MTOT * DIM];

// ---------------------------------------------------------------------------
// fp32 -> fp16 conversion (grid-stride over float4)
// ---------------------------------------------------------------------------
__global__ void f2h_kernel(const float* __restrict__ s, __half* __restrict__ d, int n4)
{
    int i = blockIdx.x * blockDim.x + threadIdx.x;
    if (i < n4) {
        float4 v = ((const float4*)s)[i];
        __half2 a = __floats2half2_rn(v.x, v.y);
        __half2 b = __floats2half2_rn(v.z, v.w);
        uint2 o;
        o.x = *(uint32_t*)&a;
        o.y = *(uint32_t*)&b;
        ((uint2*)d)[i] = o;
    }
}

// ---------------------------------------------------------------------------
// fp16 mma.sync GEMM core: C[M,N] = A[M,K] * B[N,K]^T, K=DIM fixed.
// Block 128x128, BK=32, 3-stage cp.async, 8 warps (2x4), warp tile 64x32.
// smem rows padded to 40 halves (80B) -> conflict-free ldmatrix.
// ---------------------------------------------------------------------------
#define BK       32
#define ROWP     40                      // padded row stride (halves)
#define STAGE_H  (128 * ROWP)            // halves per operand tile
#define NSTAGE   3
#define SMEM_HALVES (NSTAGE * 2 * STAGE_H)
#define SMEM_BYTES  (SMEM_HALVES * 2)    // 61440

__device__ __forceinline__ uint32_t smem_u32(const void* p) {
    uint32_t a;
    asm("{ .reg .u64 t; cvta.to.shared.u64 t, %1; cvt.u32.u64 %0, t; }"
        : "=r"(a) : "l"(p));
    return a;
}

#define CP_ASYNC(saddr, gaddr) \
    asm volatile("cp.async.cg.shared.global [%0], [%1], 16;" :: "r"(saddr), "l"(gaddr))
#define CP_COMMIT() asm volatile("cp.async.commit_group;" ::: "memory")
#define CP_WAIT1()  asm volatile("cp.async.wait_group 1;" ::: "memory")
#define CP_WAIT0()  asm volatile("cp.async.wait_group 0;" ::: "memory")

#define LDSM_X4(r0, r1, r2, r3, addr) \
    asm volatile("ldmatrix.sync.aligned.m8n8.x4.shared.b16 {%0,%1,%2,%3}, [%4];" \
        : "=r"(r0), "=r"(r1), "=r"(r2), "=r"(r3) : "r"(addr))

#define MMA_F16(c, a0, a1, a2, a3, b0, b1) \
    asm volatile("mma.sync.aligned.m16n8k16.row.col.f32.f16.f16.f32 " \
        "{%0,%1,%2,%3}, {%4,%5,%6,%7}, {%8,%9}, {%0,%1,%2,%3};" \
        : "+f"((c)[0]), "+f"((c)[1]), "+f"((c)[2]), "+f"((c)[3]) \
        : "r"(a0), "r"(a1), "r"(a2), "r"(a3), "r"(b0), "r"(b1))

// stage loader: 2 A-chunks + 2 B-chunks of 16B per thread
__device__ __forceinline__ void gemm_issue_stage(const __half* __restrict__ A,
                                                 const __half* __restrict__ B,
                                                 uint32_t smemA, uint32_t smemB,
                                                 int m0, int n0, int kt, int tid)
{
    const int row = tid >> 1;
    const int cb  = (tid & 1) * 2;
#pragma unroll
    for (int c = 0; c < 2; c++) {
        int col = (cb + c) * 8;                 // half offset in row
        uint32_t sa = smemA + (row * ROWP + col) * 2;
        const __half* ga = A + (size_t)(m0 + row) * DIM + kt * BK + col;
        CP_ASYNC(sa, ga);
        uint32_t sbb = smemB + (row * ROWP + col) * 2;
        const __half* gb = B + (size_t)(n0 + row) * DIM + kt * BK + col;
        CP_ASYNC(sbb, gb);
    }
    CP_COMMIT();
}

// compute one BK=32 stage
__device__ __forceinline__ void gemm_compute_stage(uint32_t smemA, uint32_t smemB,
                                                   float c[4][4][4],
                                                   int wm, int wn, int lane)
{
    const int grp = lane >> 3;
    const int li  = lane & 7;
    // A: row_off = (grp&1)*8 + li, k_off = (grp>>1)*8
    const int arow = wm * 64 + (grp & 1) * 8 + li;
    const int akof = (grp >> 1) * 8;
    // B: row_off = (grp>>1)*8 + li, k_off = (grp&1)*8
    const int brow = wn * 32 + (grp >> 1) * 8 + li;
    const int bkof = (grp & 1) * 8;

#pragma unroll
    for (int ks = 0; ks < 2; ks++) {
        uint32_t a[4][4];
        uint32_t b[2][4];
#pragma unroll
        for (int i = 0; i < 4; i++) {
            uint32_t addr = smemA + ((arow + i * 16) * ROWP + ks * 16 + akof) * 2;
            LDSM_X4(a[i][0], a[i][1], a[i][2], a[i][3], addr);
        }
#pragma unroll
        for (int p = 0; p < 2; p++) {
            uint32_t addr = smemB + ((brow + p * 16) * ROWP + ks * 16 + bkof) * 2;
            LDSM_X4(b[p][0], b[p][1], b[p][2], b[p][3], addr);
        }
#pragma unroll
        for (int i = 0; i < 4; i++) {
#pragma unroll
            for (int j = 0; j < 4; j++) {
                uint32_t b0 = b[j >> 1][(j & 1) * 2 + 0];
                uint32_t b1 = b[j >> 1][(j & 1) * 2 + 1];
                MMA_F16(c[i][j], a[i][0], a[i][1], a[i][2], a[i][3], b0, b1);
            }
        }
    }
}

__device__ __forceinline__ void gemm_body(const __half* __restrict__ A,
                                          const __half* __restrict__ B,
                                          float* __restrict__ C,
                                          int m0, int n0)
{
    extern __shared__ __half sh[];
    const int tid  = threadIdx.x;
    const int lane = tid & 31;
    const int wid  = tid >> 5;
    const int wm   = wid >> 2;
    const int wn   = wid & 3;

    uint32_t sA[NSTAGE], sB[NSTAGE];
#pragma unroll
    for (int s = 0; s < NSTAGE; s++) {
        sA[s] = smem_u32(sh + s * 2 * STAGE_H);
        sB[s] = smem_u32(sh + s * 2 * STAGE_H + STAGE_H);
    }

    float c[4][4][4];
#pragma unroll
    for (int i = 0; i < 4; i++)
#pragma unroll
        for (int j = 0; j < 4; j++)
#pragma unroll
            for (int e = 0; e < 4; e++) c[i][j][e] = 0.0f;

    const int NIT = DIM / BK;   // 64

    gemm_issue_stage(A, B, sA[0], sB[0], m0, n0, 0, tid);
    gemm_issue_stage(A, B, sA[1], sB[1], m0, n0, 1, tid);

#pragma unroll 1
    for (int kt = 0; kt < NIT; kt++) {
        if (kt + 2 < NIT) CP_WAIT1(); else CP_WAIT0();
        __syncthreads();
        if (kt + 2 < NIT)
            gemm_issue_stage(A, B, sA[(kt + 2) % 3], sB[(kt + 2) % 3],
                             m0, n0, kt + 2, tid);
        gemm_compute_stage(sA[kt % 3], sB[kt % 3], c, wm, wn, lane);
        __syncthreads();
    }

    const int g = lane >> 2;
    const int t = lane & 3;
#pragma unroll
    for (int i = 0; i < 4; i++) {
        int mbase = m0 + wm * 64 + i * 16;
#pragma unroll
        for (int j = 0; j < 4; j++) {
            int ncol = n0 + wn * 32 + j * 8 + t * 2;
            *(float2*)&C[(size_t)(mbase + g) * DIM + ncol] =
                make_float2(c[i][j][0], c[i][j][1]);
            *(float2*)&C[(size_t)(mbase + g + 8) * DIM + ncol] =
                make_float2(c[i][j][2], c[i][j][3]);
        }
    }
}

// Fused QKV projection: grid.x in [0,48): [0,16)->Q, [16,32)->K, [32,48)->V
__global__ __launch_bounds__(256) void gemm_qkv(const __half* __restrict__ xh)
{
    const int which = blockIdx.x >> 4;
    const int n0 = (blockIdx.x & 15) * 128;
    const int m0 = blockIdx.y * 128;
    const __half* B = (which == 0) ? g_Wqh : (which == 1) ? g_Wkh : g_Wvh;
    float* C = (which == 0) ? g_Q : (which == 1) ? g_K : g_V;
    gemm_body(xh, B, C, m0, n0);
}

// Generic: C = A * B^T
__global__ __launch_bounds__(256) void gemm_nt(const __half* __restrict__ A,
                                               const __half* __restrict__ B,
                                               float* __restrict__ C)
{
    gemm_body(A, B, C, blockIdx.y * 128, blockIdx.x * 128);
}

// ---------------------------------------------------------------------------
// Per-head RMSNorm + RoPE (in place on fp32). One warp per head.
// ---------------------------------------------------------------------------
__global__ __launch_bounds__(128) void rmsnorm_rope(float* __restrict__ T)
{
    const int b = blockIdx.z;
    const int s = blockIdx.y;
    const int warp = threadIdx.x >> 5;
    const int lane = threadIdx.x & 31;
    const int h = blockIdx.x * 4 + warp;

    float* row = T + ((size_t)(b * SEQ + s)) * DIM + h * HDIM;

    float x1a = row[lane];
    float x1b = row[lane + 32];
    float x2a = row[lane + 64];
    float x2b = row[lane + 96];

    float ss = x1a * x1a + x1b * x1b + x2a * x2a + x2b * x2b;
#pragma unroll
    for (int off = 16; off > 0; off >>= 1)
        ss += __shfl_xor_sync(0xffffffffu, ss, off);

    float rnorm = rsqrtf(ss * (1.0f / 128.0f) + EPSV);
    x1a *= rnorm; x1b *= rnorm; x2a *= rnorm; x2b *= rnorm;

    const float LN1E4 = 9.210340371976184f;
    float pos = (float)s;

    {
        float expo = (float)lane * (1.0f / 64.0f);
        float ang = pos * __expf(-expo * LN1E4);
        float sn, cs;
        sincosf(ang, &sn, &cs);
        row[lane]      =  x1a * cs + x2a * sn;
        row[lane + 64] = -x1a * sn + x2a * cs;
    }
    {
        float expo = (float)(lane + 32) * (1.0f / 64.0f);
        float ang = pos * __expf(-expo * LN1E4);
        float sn, cs;
        sincosf(ang, &sn, &cs);
        row[lane + 32] =  x1b * cs + x2b * sn;
        row[lane + 96] = -x1b * sn + x2b * cs;
    }
}

// ---------------------------------------------------------------------------
// Causal flash attention, fp32 math; epilogue writes Y as fp16.
// ---------------------------------------------------------------------------
__global__ __launch_bounds__(256) void attn_kernel(const float* __restrict__ Q,
                                                   const float* __restrict__ K,
                                                   const float* __restrict__ V,
                                                   __half* __restrict__ Yh)
{
    __shared__ float4 Ks[32][32];
    __shared__ float4 Vs[32][32];
    __shared__ float  Ss[32][128];

    const int tid = threadIdx.x;
    const int b = blockIdx.z;
    const int h = blockIdx.y;
    const int m0 = blockIdx.x * 128;
    const int row = tid >> 1;
    const int hf = tid & 1;
    const int r = m0 + row;

    const float* qrow = Q + ((size_t)(b * SEQ + r)) * DIM + h * HDIM + hf * 64;
    float4 q[16];
#pragma unroll
    for (int i = 0; i < 16; i++) q[i] = ((const float4*)qrow)[i];

    float4 acc[16];
#pragma unroll
    for (int i = 0; i < 16; i++) acc[i] = make_float4(0.f, 0.f, 0.f, 0.f);

    float mI = -1e30f, lI = 0.0f;
    const float scale = 0.08838834764831845f;
    const int nEnd = m0 + 128;

    for (int n0 = 0; n0 < nEnd; n0 += 32) {
        __syncthreads();
#pragma unroll
        for (int e = 0; e < 4; e++) {
            int idx = tid + e * 256;
            int j = idx >> 5;
            int dv = idx & 31;
            size_t gofs = ((size_t)(b * SEQ + n0 + j)) * DIM + h * HDIM + dv * 4;
            Ks[j][dv] = *(const float4*)(K + gofs);
            Vs[j][dv] = *(const float4*)(V + gofs);
        }
        __syncthreads();

        float mTile = -1e30f;
#pragma unroll
        for (int j = 0; j < 32; j++) {
            float s = 0.0f;
#pragma unroll
            for (int i = 0; i < 16; i++) {
                float4 kv = Ks[j][hf * 16 + i];
                float4 qq = q[i];
                s = fmaf(qq.x, kv.x, s);
                s = fmaf(qq.y, kv.y, s);
                s = fmaf(qq.z, kv.z, s);
                s = fmaf(qq.w, kv.w, s);
            }
            s += __shfl_xor_sync(0xffffffffu, s, 1);
            s *= scale;
            if (n0 + j > r) s = -1e30f;
            mTile = fmaxf(mTile, s);
            if (hf == 0) Ss[j][row] = s;
        }
        __syncwarp();

        float mNew = fmaxf(mI, mTile);
        float resc = __expf(mI - mNew);
        mI = mNew;
        lI *= resc;
#pragma unroll
        for (int i = 0; i < 16; i++) {
            acc[i].x *= resc; acc[i].y *= resc;
            acc[i].z *= resc; acc[i].w *= resc;
        }

#pragma unroll
        for (int j = 0; j < 32; j++) {
            float p = __expf(Ss[j][row] - mNew);
            lI += p;
#pragma unroll
            for (int i = 0; i < 16; i++) {
                float4 vv = Vs[j][hf * 16 + i];
                acc[i].x = fmaf(p, vv.x, acc[i].x);
                acc[i].y = fmaf(p, vv.y, acc[i].y);
                acc[i].z = fmaf(p, vv.z, acc[i].z);
                acc[i].w = fmaf(p, vv.w, acc[i].w);
            }
        }
    }

    float inv = 1.0f / lI;
    __half* yrow = Yh + ((size_t)(b * SEQ + r)) * DIM + h * HDIM + hf * 64;
#pragma unroll
    for (int i = 0; i < 16; i++) {
        __half2 h01 = __floats2half2_rn(acc[i].x * inv, acc[i].y * inv);
        __half2 h23 = __floats2half2_rn(acc[i].z * inv, acc[i].w * inv);
        uint2 o;
        o.x = *(uint32_t*)&h01;
        o.y = *(uint32_t*)&h23;
        ((uint2*)yrow)[i] = o;
    }
}

// ---------------------------------------------------------------------------
// Launch
// ---------------------------------------------------------------------------
extern "C" void kernel_launch(void* const* d_in, const int* in_sizes, int n_in,
                              void* d_out, int out_size)
{
    const float* x  = (const float*)d_in[0];
    const float* Wq = (const float*)d_in[1];
    const float* Wk = (const float*)d_in[2];
    const float* Wv = (const float*)d_in[3];
    const float* Wo = (const float*)d_in[4];
    float* out = (float*)d_out;

    float* Qp; cudaGetSymbolAddress((void**)&Qp, g_Q);
    float* Kp; cudaGetSymbolAddress((void**)&Kp, g_K);
    float* Vp; cudaGetSymbolAddress((void**)&Vp, g_V);
    __half* xh;  cudaGetSymbolAddress((void**)&xh,  g_xh);
    __half* wqh; cudaGetSymbolAddress((void**)&wqh, g_Wqh);
    __half* wkh; cudaGetSymbolAddress((void**)&wkh, g_Wkh);
    __half* wvh; cudaGetSymbolAddress((void**)&wvh, g_Wvh);
    __half* woh; cudaGetSymbolAddress((void**)&woh, g_Woh);
    __half* yh;  cudaGetSymbolAddress((void**)&yh,  g_Yh);

    cudaFuncSetAttribute(gemm_qkv, cudaFuncAttributeMaxDynamicSharedMemorySize, SMEM_BYTES);
    cudaFuncSetAttribute(gemm_nt,  cudaFuncAttributeMaxDynamicSharedMemorySize, SMEM_BYTES);

    // fp32 -> fp16 conversions
    const int nX = MTOT * DIM / 4, nW = DIM * DIM / 4;
    f2h_kernel<<<(nX + 255) / 256, 256>>>(x,  xh,  nX);
    f2h_kernel<<<(nW + 255) / 256, 256>>>(Wq, wqh, nW);
    f2h_kernel<<<(nW + 255) / 256, 256>>>(Wk, wkh, nW);
    f2h_kernel<<<(nW + 255) / 256, 256>>>(Wv, wvh, nW);
    f2h_kernel<<<(nW + 255) / 256, 256>>>(Wo, woh, nW);

    // fused QKV projection
    dim3 gQKV(48, MTOT / 128);
    gemm_qkv<<<gQKV, 256, SMEM_BYTES>>>(xh);

    dim3 gNorm(NHEAD / 4, SEQ, BATCH);
    rmsnorm_rope<<<gNorm, 128>>>(Qp);
    rmsnorm_rope<<<gNorm, 128>>>(Kp);

    dim3 gAttn(SEQ / 128, NHEAD, BATCH);
    attn_kernel<<<gAttn, 256>>>(Qp, Kp, Vp, yh);

    dim3 gO(DIM / 128, MTOT / 128);
    gemm_nt<<<gO, 256, SMEM_BYTES>>>(yh, woh, out);
}

// round 5
// speedup vs baseline: 7.6491x; 4.3144x over previous
#include <cuda_runtime.h>
#include <cuda_fp16.h>
#include <math.h>
#include <stdint.h>

#define BATCH 2
#define SEQ   2048
#define DIM   2048
#define NHEAD 16
#define HDIM  128
#define MTOT  (BATCH * SEQ)
#define EPSV  1.1920928955078125e-07f
#define LOG2E 1.4426950408889634f

// fp32 scratch
__device__ float g_Q[MTOT * DIM];
__device__ float g_K[MTOT * DIM];
__device__ float g_V[MTOT * DIM];
// fp16 operands
__device__ __half g_xh[MTOT * DIM];
__device__ __half g_Wqh[DIM * DIM];
__device__ __half g_Wkh[DIM * DIM];
__device__ __half g_Wvh[DIM * DIM];
__device__ __half g_Woh[DIM * DIM];
__device__ __half g_Yh[MTOT * DIM];
__device__ __half g_Qh[MTOT * DIM];
__device__ __half g_Kh[MTOT * DIM];
__device__ __half g_Vth[MTOT * DIM];   // [b*DIM + (h*128+d)][seq]

// ---------------------------------------------------------------------------
__global__ void f2h_kernel(const float* __restrict__ s, __half* __restrict__ d, int n4)
{
    int i = blockIdx.x * blockDim.x + threadIdx.x;
    if (i < n4) {
        float4 v = ((const float4*)s)[i];
        __half2 a = __floats2half2_rn(v.x, v.y);
        __half2 b = __floats2half2_rn(v.z, v.w);
        uint2 o;
        o.x = *(uint32_t*)&a;
        o.y = *(uint32_t*)&b;
        ((uint2*)d)[i] = o;
    }
}

// ---------------------------------------------------------------------------
// PTX helpers
// ---------------------------------------------------------------------------
__device__ __forceinline__ uint32_t smem_u32(const void* p) {
    uint32_t a;
    asm("{ .reg .u64 t; cvta.to.shared.u64 t, %1; cvt.u32.u64 %0, t; }"
        : "=r"(a) : "l"(p));
    return a;
}
#define CP_ASYNC(saddr, gaddr) \
    asm volatile("cp.async.cg.shared.global [%0], [%1], 16;" :: "r"(saddr), "l"(gaddr))
#define CP_COMMIT() asm volatile("cp.async.commit_group;" ::: "memory")
#define CP_WAIT1()  asm volatile("cp.async.wait_group 1;" ::: "memory")
#define CP_WAIT0()  asm volatile("cp.async.wait_group 0;" ::: "memory")
#define LDSM_X4(r0, r1, r2, r3, addr) \
    asm volatile("ldmatrix.sync.aligned.m8n8.x4.shared.b16 {%0,%1,%2,%3}, [%4];" \
        : "=r"(r0), "=r"(r1), "=r"(r2), "=r"(r3) : "r"(addr))
#define MMA_F16(c, a0, a1, a2, a3, b0, b1) \
    asm volatile("mma.sync.aligned.m16n8k16.row.col.f32.f16.f16.f32 " \
        "{%0,%1,%2,%3}, {%4,%5,%6,%7}, {%8,%9}, {%0,%1,%2,%3};" \
        : "+f"((c)[0]), "+f"((c)[1]), "+f"((c)[2]), "+f"((c)[3]) \
        : "r"(a0), "r"(a1), "r"(a2), "r"(a3), "r"(b0), "r"(b1))

__device__ __forceinline__ uint32_t packh2(float x, float y) {
    __half2 h = __floats2half2_rn(x, y);
    return *(uint32_t*)&h;
}

// ===========================================================================
// fp16 GEMM (unchanged from R4): C[M,N] = A[M,K]*B[N,K]^T
// ===========================================================================
#define BK       32
#define ROWP     40
#define STAGE_H  (128 * ROWP)
#define NSTAGE   3
#define SMEM_BYTES (NSTAGE * 2 * STAGE_H * 2)

__device__ __forceinline__ void gemm_issue_stage(const __half* __restrict__ A,
                                                 const __half* __restrict__ B,
                                                 uint32_t smemA, uint32_t smemB,
                                                 int m0, int n0, int kt, int tid)
{
    const int row = tid >> 1;
    const int cb  = (tid & 1) * 2;
#pragma unroll
    for (int c = 0; c < 2; c++) {
        int col = (cb + c) * 8;
        CP_ASYNC(smemA + (row * ROWP + col) * 2,
                 A + (size_t)(m0 + row) * DIM + kt * BK + col);
        CP_ASYNC(smemB + (row * ROWP + col) * 2,
                 B + (size_t)(n0 + row) * DIM + kt * BK + col);
    }
    CP_COMMIT();
}

__device__ __forceinline__ void gemm_compute_stage(uint32_t smemA, uint32_t smemB,
                                                   float c[4][4][4],
                                                   int wm, int wn, int lane)
{
    const int grp = lane >> 3;
    const int li  = lane & 7;
    const int arow = wm * 64 + (grp & 1) * 8 + li;
    const int akof = (grp >> 1) * 8;
    const int brow = wn * 32 + (grp >> 1) * 8 + li;
    const int bkof = (grp & 1) * 8;

#pragma unroll
    for (int ks = 0; ks < 2; ks++) {
        uint32_t a[4][4];
        uint32_t b[2][4];
#pragma unroll
        for (int i = 0; i < 4; i++)
            LDSM_X4(a[i][0], a[i][1], a[i][2], a[i][3],
                    smemA + ((arow + i * 16) * ROWP + ks * 16 + akof) * 2);
#pragma unroll
        for (int p = 0; p < 2; p++)
            LDSM_X4(b[p][0], b[p][1], b[p][2], b[p][3],
                    smemB + ((brow + p * 16) * ROWP + ks * 16 + bkof) * 2);
#pragma unroll
        for (int i = 0; i < 4; i++)
#pragma unroll
            for (int j = 0; j < 4; j++)
                MMA_F16(c[i][j], a[i][0], a[i][1], a[i][2], a[i][3],
                        b[j >> 1][(j & 1) * 2 + 0], b[j >> 1][(j & 1) * 2 + 1]);
    }
}

__device__ __forceinline__ void gemm_body(const __half* __restrict__ A,
                                          const __half* __restrict__ B,
                                          float* __restrict__ C,
                                          int m0, int n0)
{
    extern __shared__ __half sh[];
    const int tid  = threadIdx.x;
    const int lane = tid & 31;
    const int wid  = tid >> 5;
    const int wm   = wid >> 2;
    const int wn   = wid & 3;

    uint32_t sA[NSTAGE], sB[NSTAGE];
#pragma unroll
    for (int s = 0; s < NSTAGE; s++) {
        sA[s] = smem_u32(sh + s * 2 * STAGE_H);
        sB[s] = smem_u32(sh + s * 2 * STAGE_H + STAGE_H);
    }

    float c[4][4][4];
#pragma unroll
    for (int i = 0; i < 4; i++)
#pragma unroll
        for (int j = 0; j < 4; j++)
#pragma unroll
            for (int e = 0; e < 4; e++) c[i][j][e] = 0.0f;

    const int NIT = DIM / BK;

    gemm_issue_stage(A, B, sA[0], sB[0], m0, n0, 0, tid);
    gemm_issue_stage(A, B, sA[1], sB[1], m0, n0, 1, tid);

#pragma unroll 1
    for (int kt = 0; kt < NIT; kt++) {
        if (kt + 2 < NIT) CP_WAIT1(); else CP_WAIT0();
        __syncthreads();
        if (kt + 2 < NIT)
            gemm_issue_stage(A, B, sA[(kt + 2) % 3], sB[(kt + 2) % 3],
                             m0, n0, kt + 2, tid);
        gemm_compute_stage(sA[kt % 3], sB[kt % 3], c, wm, wn, lane);
        __syncthreads();
    }

    const int g = lane >> 2;
    const int t = lane & 3;
#pragma unroll
    for (int i = 0; i < 4; i++) {
        int mbase = m0 + wm * 64 + i * 16;
#pragma unroll
        for (int j = 0; j < 4; j++) {
            int ncol = n0 + wn * 32 + j * 8 + t * 2;
            *(float2*)&C[(size_t)(mbase + g) * DIM + ncol] =
                make_float2(c[i][j][0], c[i][j][1]);
            *(float2*)&C[(size_t)(mbase + g + 8) * DIM + ncol] =
                make_float2(c[i][j][2], c[i][j][3]);
        }
    }
}

__global__ __launch_bounds__(256) void gemm_qkv(const __half* __restrict__ xh)
{
    const int which = blockIdx.x >> 4;
    const int n0 = (blockIdx.x & 15) * 128;
    const int m0 = blockIdx.y * 128;
    const __half* B = (which == 0) ? g_Wqh : (which == 1) ? g_Wkh : g_Wvh;
    float* C = (which == 0) ? g_Q : (which == 1) ? g_K : g_V;
    gemm_body(xh, B, C, m0, n0);
}

__global__ __launch_bounds__(256) void gemm_nt(const __half* __restrict__ A,
                                               const __half* __restrict__ B,
                                               float* __restrict__ C)
{
    gemm_body(A, B, C, blockIdx.y * 128, blockIdx.x * 128);
}

// ---------------------------------------------------------------------------
// RMSNorm + RoPE, fp32 in -> fp16 out (with optional folded scale).
// ---------------------------------------------------------------------------
__global__ __launch_bounds__(128) void rmsnorm_rope_h(const float* __restrict__ In,
                                                      __half* __restrict__ Out,
                                                      float outscale)
{
    const int b = blockIdx.z;
    const int s = blockIdx.y;
    const int warp = threadIdx.x >> 5;
    const int lane = threadIdx.x & 31;
    const int h = blockIdx.x * 4 + warp;

    const float* row = In + ((size_t)(b * SEQ + s)) * DIM + h * HDIM;
    __half* orow = Out + ((size_t)(b * SEQ + s)) * DIM + h * HDIM;

    float x1a = row[lane];
    float x1b = row[lane + 32];
    float x2a = row[lane + 64];
    float x2b = row[lane + 96];

    float ss = x1a * x1a + x1b * x1b + x2a * x2a + x2b * x2b;
#pragma unroll
    for (int off = 16; off > 0; off >>= 1)
        ss += __shfl_xor_sync(0xffffffffu, ss, off);

    float rnorm = rsqrtf(ss * (1.0f / 128.0f) + EPSV) * outscale;
    x1a *= rnorm; x1b *= rnorm; x2a *= rnorm; x2b *= rnorm;

    const float LN1E4 = 9.210340371976184f;
    float pos = (float)s;

    {
        float ang = pos * __expf(-(float)lane * (1.0f / 64.0f) * LN1E4);
        float sn, cs;
        sincosf(ang, &sn, &cs);
        orow[lane]      = __float2half_rn( x1a * cs + x2a * sn);
        orow[lane + 64] = __float2half_rn(-x1a * sn + x2a * cs);
    }
    {
        float ang = pos * __expf(-(float)(lane + 32) * (1.0f / 64.0f) * LN1E4);
        float sn, cs;
        sincosf(ang, &sn, &cs);
        orow[lane + 32] = __float2half_rn( x1b * cs + x2b * sn);
        orow[lane + 96] = __float2half_rn(-x1b * sn + x2b * cs);
    }
}

// ---------------------------------------------------------------------------
// V transpose: g_V fp32 [b*SEQ+s][x] -> g_Vth fp16 [b*DIM + x][s]
// ---------------------------------------------------------------------------
__global__ __launch_bounds__(256) void vtrans(const float* __restrict__ V,
                                              __half* __restrict__ Vt)
{
    __shared__ float tile[32][33];
    const int b = blockIdx.z;
    const int s0 = blockIdx.x * 32;
    const int x0 = blockIdx.y * 32;
    const int tx = threadIdx.x;
    const int ty = threadIdx.y;
#pragma unroll
    for (int k = 0; k < 4; k++)
        tile[ty + 8 * k][tx] =
            V[(size_t)(b * SEQ + s0 + ty + 8 * k) * DIM + x0 + tx];
    __syncthreads();
#pragma unroll
    for (int k = 0; k < 4; k++) {
        int x = x0 + ty + 8 * k;
        Vt[(size_t)(b * DIM + x) * SEQ + s0 + tx] =
            __float2half_rn(tile[tx][ty + 8 * k]);
    }
}

// ===========================================================================
// Tensor-core causal flash attention.
// CTA: 128 q-rows x one (b,h). 8 warps, 16 rows each. BN=64 keys/tile.
// ===========================================================================
#define BN    64
#define ROWQ  136     // halves per Q/K smem row (d-major)
#define ROWV  72      // halves per Vt smem row (key-major)
#define AQ_OFF  0
#define AK_OFF  17408                       // 128*136
#define AK_SZ   (64 * ROWQ)                 // 8704
#define AV_OFF  (AK_OFF + 2 * AK_SZ)        // 34816
#define AV_SZ   (128 * ROWV)                // 9216
#define ATT_SMEM ((AV_OFF + 2 * AV_SZ) * 2) // 106496 bytes

__global__ __launch_bounds__(256, 1) void attn_tc(const __half* __restrict__ Qh,
                                                  const __half* __restrict__ Kh,
                                                  const __half* __restrict__ Vth,
                                                  __half* __restrict__ Yh)
{
    extern __shared__ __half ash[];
    const int tid  = threadIdx.x;
    const int lane = tid & 31;
    const int wid  = tid >> 5;          // warp m-index 0..7
    const int b = blockIdx.z;
    const int h = blockIdx.y;
    const int m0 = blockIdx.x * 128;
    const size_t bS = (size_t)b * SEQ;

    const uint32_t sQ = smem_u32(ash);
    uint32_t sK[2] = { smem_u32(ash + AK_OFF), smem_u32(ash + AK_OFF + AK_SZ) };
    uint32_t sV[2] = { smem_u32(ash + AV_OFF), smem_u32(ash + AV_OFF + AV_SZ) };

    const __half* Qg = Qh + (bS + m0) * DIM + h * HDIM;
    const __half* Kg = Kh + bS * DIM + h * HDIM;
    const __half* Vg = Vth + ((size_t)b * DIM + h * HDIM) * SEQ;

    // ---- staging lambdas ----
    // Q: 128 rows x 128 halves
    {
        const int row = tid >> 1;
        const int cb = (tid & 1) * 8;
#pragma unroll
        for (int c = 0; c < 8; c += 1) {
            // 8 chunks per thread: rows tid>>1, cols interleaved
        }
    }
    // (Q staged below together with tile 0)

    const int T = blockIdx.x * 2 + 2;     // key tiles

    // issue group 0: Q + K/V tile 0
    {
        const int row = tid >> 4;         // 0..15
        const int cq  = tid & 15;         // 0..15
#pragma unroll
        for (int i = 0; i < 8; i++) {     // Q: 128 rows
            int r = row + i * 16;
            CP_ASYNC(sQ + (r * ROWQ + cq * 8) * 2, Qg + (size_t)r * DIM + cq * 8);
        }
#pragma unroll
        for (int i = 0; i < 4; i++) {     // K tile 0: 64 rows
            int r = row + i * 16;
            CP_ASYNC(sK[0] + (r * ROWQ + cq * 8) * 2, Kg + (size_t)r * DIM + cq * 8);
        }
        const int vrow = tid >> 3;        // 0..31
        const int vq   = tid & 7;
#pragma unroll
        for (int i = 0; i < 4; i++) {     // V tile 0: 128 d-rows x 64
            int r = vrow + i * 32;
            CP_ASYNC(sV[0] + (r * ROWV + vq * 8) * 2, Vg + (size_t)r * SEQ + vq * 8);
        }
        CP_COMMIT();
        if (1 < T) {
            int n0 = 64;
#pragma unroll
            for (int i = 0; i < 4; i++) {
                int r = row + i * 16;
                CP_ASYNC(sK[1] + (r * ROWQ + cq * 8) * 2,
                         Kg + (size_t)(n0 + r) * DIM + cq * 8);
            }
#pragma unroll
            for (int i = 0; i < 4; i++) {
                int r = vrow + i * 32;
                CP_ASYNC(sV[1] + (r * ROWV + vq * 8) * 2,
                         Vg + (size_t)r * SEQ + n0 + vq * 8);
            }
            CP_COMMIT();
        }
    }

    const int grp = lane >> 3;
    const int li  = lane & 7;
    const int r0 = m0 + wid * 16 + (lane >> 2);
    const int r1 = r0 + 8;

    float Of[16][4];
#pragma unroll
    for (int j = 0; j < 16; j++)
#pragma unroll
        for (int e = 0; e < 4; e++) Of[j][e] = 0.0f;
    float mx0 = -1e30f, mx1 = -1e30f, l0 = 0.0f, l1 = 0.0f;

#pragma unroll 1
    for (int t = 0; t < T; t++) {
        if (t + 1 < T) CP_WAIT1(); else CP_WAIT0();
        __syncthreads();

        const int n0 = t * BN;
        const bool skip = (n0 > m0 + wid * 16 + 15);
        if (!skip) {
            const uint32_t kb = sK[t & 1];
            const uint32_t vb = sV[t & 1];

            float sf[8][4];
#pragma unroll
            for (int f = 0; f < 8; f++)
#pragma unroll
                for (int e = 0; e < 4; e++) sf[f][e] = 0.0f;

            // S = Q K^T
#pragma unroll
            for (int ks = 0; ks < 8; ks++) {
                uint32_t a0, a1, a2, a3;
                LDSM_X4(a0, a1, a2, a3,
                        sQ + (((wid * 16 + (grp & 1) * 8 + li)) * ROWQ
                              + ks * 16 + (grp >> 1) * 8) * 2);
#pragma unroll
                for (int p = 0; p < 4; p++) {
                    uint32_t b0, b1, b2, b3;
                    LDSM_X4(b0, b1, b2, b3,
                            kb + (((grp >> 1) * 8 + li + p * 16) * ROWQ
                                  + ks * 16 + (grp & 1) * 8) * 2);
                    MMA_F16(sf[2 * p],     a0, a1, a2, a3, b0, b1);
                    MMA_F16(sf[2 * p + 1], a0, a1, a2, a3, b2, b3);
                }
            }

            // causal mask
            if (n0 + 63 > m0 + wid * 16) {
#pragma unroll
                for (int f = 0; f < 8; f++) {
                    int c0 = n0 + f * 8 + (lane & 3) * 2;
                    if (c0 > r0)     sf[f][0] = -1e30f;
                    if (c0 + 1 > r0) sf[f][1] = -1e30f;
                    if (c0 > r1)     sf[f][2] = -1e30f;
                    if (c0 + 1 > r1) sf[f][3] = -1e30f;
                }
            }

            // row stats
            float mt0 = -1e30f, mt1 = -1e30f;
#pragma unroll
            for (int f = 0; f < 8; f++) {
                mt0 = fmaxf(mt0, fmaxf(sf[f][0], sf[f][1]));
                mt1 = fmaxf(mt1, fmaxf(sf[f][2], sf[f][3]));
            }
            mt0 = fmaxf(mt0, __shfl_xor_sync(0xffffffffu, mt0, 1));
            mt0 = fmaxf(mt0, __shfl_xor_sync(0xffffffffu, mt0, 2));
            mt1 = fmaxf(mt1, __shfl_xor_sync(0xffffffffu, mt1, 1));
            mt1 = fmaxf(mt1, __shfl_xor_sync(0xffffffffu, mt1, 2));

            float mn0 = fmaxf(mx0, mt0);
            float mn1 = fmaxf(mx1, mt1);
            float al0 = exp2f((mx0 - mn0) * LOG2E);
            float al1 = exp2f((mx1 - mn1) * LOG2E);
            mx0 = mn0; mx1 = mn1;

            float rs0 = 0.0f, rs1 = 0.0f;
#pragma unroll
            for (int f = 0; f < 8; f++) {
                sf[f][0] = exp2f((sf[f][0] - mn0) * LOG2E);
                sf[f][1] = exp2f((sf[f][1] - mn0) * LOG2E);
                sf[f][2] = exp2f((sf[f][2] - mn1) * LOG2E);
                sf[f][3] = exp2f((sf[f][3] - mn1) * LOG2E);
                rs0 += sf[f][0] + sf[f][1];
                rs1 += sf[f][2] + sf[f][3];
            }
            rs0 += __shfl_xor_sync(0xffffffffu, rs0, 1);
            rs0 += __shfl_xor_sync(0xffffffffu, rs0, 2);
            rs1 += __shfl_xor_sync(0xffffffffu, rs1, 1);
            rs1 += __shfl_xor_sync(0xffffffffu, rs1, 2);
            l0 = l0 * al0 + rs0;
            l1 = l1 * al1 + rs1;

#pragma unroll
            for (int j = 0; j < 16; j++) {
                Of[j][0] *= al0; Of[j][1] *= al0;
                Of[j][2] *= al1; Of[j][3] *= al1;
            }

            // O += P V
#pragma unroll
            for (int ks2 = 0; ks2 < 4; ks2++) {
                uint32_t pa0 = packh2(sf[2 * ks2][0],     sf[2 * ks2][1]);
                uint32_t pa1 = packh2(sf[2 * ks2][2],     sf[2 * ks2][3]);
                uint32_t pa2 = packh2(sf[2 * ks2 + 1][0], sf[2 * ks2 + 1][1]);
                uint32_t pa3 = packh2(sf[2 * ks2 + 1][2], sf[2 * ks2 + 1][3]);
#pragma unroll
                for (int p = 0; p < 8; p++) {
                    uint32_t b0, b1, b2, b3;
                    LDSM_X4(b0, b1, b2, b3,
                            vb + (((grp >> 1) * 8 + li + p * 16) * ROWV
                                  + ks2 * 16 + (grp & 1) * 8) * 2);
                    MMA_F16(Of[2 * p],     pa0, pa1, pa2, pa3, b0, b1);
                    MMA_F16(Of[2 * p + 1], pa0, pa1, pa2, pa3, b2, b3);
                }
            }
        }

        __syncthreads();
        if (t + 2 < T) {
            const int nn = (t + 2) * BN;
            const int row = tid >> 4;
            const int cq  = tid & 15;
            const uint32_t kb2 = sK[t & 1];
            const uint32_t vb2 = sV[t & 1];
#pragma unroll
            for (int i = 0; i < 4; i++) {
                int r = row + i * 16;
                CP_ASYNC(kb2 + (r * ROWQ + cq * 8) * 2,
                         Kg + (size_t)(nn + r) * DIM + cq * 8);
            }
            const int vrow = tid >> 3;
            const int vq   = tid & 7;
#pragma unroll
            for (int i = 0; i < 4; i++) {
                int r = vrow + i * 32;
                CP_ASYNC(vb2 + (r * ROWV + vq * 8) * 2,
                         Vg + (size_t)r * SEQ + nn + vq * 8);
            }
            CP_COMMIT();
        }
    }

    // normalize + store fp16
    float inv0 = 1.0f / l0;
    float inv1 = 1.0f / l1;
#pragma unroll
    for (int j = 0; j < 16; j++) {
        int c = h * HDIM + j * 8 + (lane & 3) * 2;
        __half2 o0 = __floats2half2_rn(Of[j][0] * inv0, Of[j][1] * inv0);
        __half2 o1 = __floats2half2_rn(Of[j][2] * inv1, Of[j][3] * inv1);
        *(uint32_t*)&Yh[(bS + r0) * DIM + c] = *(uint32_t*)&o0;
        *(uint32_t*)&Yh[(bS + r1) * DIM + c] = *(uint32_t*)&o1;
    }
}

// ---------------------------------------------------------------------------
extern "C" void kernel_launch(void* const* d_in, const int* in_sizes, int n_in,
                              void* d_out, int out_size)
{
    const float* x  = (const float*)d_in[0];
    const float* Wq = (const float*)d_in[1];
    const float* Wk = (const float*)d_in[2];
    const float* Wv = (const float*)d_in[3];
    const float* Wo = (const float*)d_in[4];
    float* out = (float*)d_out;

    float* Qp; cudaGetSymbolAddress((void**)&Qp, g_Q);
    float* Kp; cudaGetSymbolAddress((void**)&Kp, g_K);
    float* Vp; cudaGetSymbolAddress((void**)&Vp, g_V);
    __half* xh;  cudaGetSymbolAddress((void**)&xh,  g_xh);
    __half* wqh; cudaGetSymbolAddress((void**)&wqh, g_Wqh);
    __half* wkh; cudaGetSymbolAddress((void**)&wkh, g_Wkh);
    __half* wvh; cudaGetSymbolAddress((void**)&wvh, g_Wvh);
    __half* woh; cudaGetSymbolAddress((void**)&woh, g_Woh);
    __half* yh;  cudaGetSymbolAddress((void**)&yh,  g_Yh);
    __half* qh;  cudaGetSymbolAddress((void**)&qh,  g_Qh);
    __half* kh;  cudaGetSymbolAddress((void**)&kh,  g_Kh);
    __half* vth; cudaGetSymbolAddress((void**)&vth, g_Vth);

    cudaFuncSetAttribute(gemm_qkv, cudaFuncAttributeMaxDynamicSharedMemorySize, SMEM_BYTES);
    cudaFuncSetAttribute(gemm_nt,  cudaFuncAttributeMaxDynamicSharedMemorySize, SMEM_BYTES);
    cudaFuncSetAttribute(attn_tc,  cudaFuncAttributeMaxDynamicSharedMemorySize, ATT_SMEM);

    const int nX = MTOT * DIM / 4, nW = DIM * DIM / 4;
    f2h_kernel<<<(nX + 255) / 256, 256>>>(x,  xh,  nX);
    f2h_kernel<<<(nW + 255) / 256, 256>>>(Wq, wqh, nW);
    f2h_kernel<<<(nW + 255) / 256, 256>>>(Wk, wkh, nW);
    f2h_kernel<<<(nW + 255) / 256, 256>>>(Wv, wvh, nW);
    f2h_kernel<<<(nW + 255) / 256, 256>>>(Wo, woh, nW);

    dim3 gQKV(48, MTOT / 128);
    gemm_qkv<<<gQKV, 256, SMEM_BYTES>>>(xh);

    dim3 gNorm(NHEAD / 4, SEQ, BATCH);
    rmsnorm_rope_h<<<gNorm, 128>>>(Qp, qh, 0.08838834764831845f);
    rmsnorm_rope_h<<<gNorm, 128>>>(Kp, kh, 1.0f);

    dim3 gVT(SEQ / 32, DIM / 32, BATCH);
    vtrans<<<gVT, dim3(32, 8)>>>(Vp, vth);

    dim3 gAttn(SEQ / 128, NHEAD, BATCH);
    attn_tc<<<gAttn, 256, ATT_SMEM>>>(qh, kh, vth, yh);

    dim3 gO(DIM / 128, MTOT / 128);
    gemm_nt<<<gO, 256, SMEM_BYTES>>>(yh, woh, out);
}